// round 14
// baseline (speedup 1.0000x reference)
#include <cuda_runtime.h>
#include <math.h>

#define B 128
#define C 6
#define H 224
#define W 224
#define HWSZ (H*W)          // 50176
#define HW4 (HWSZ/4)        // 12544 float4 per channel
#define POOL 7
#define NS (POOL*POOL)      // 49
#define BC (B*C)            // 768
#define CS (C*NS)           // 294
#define FEAT (3*C)          // 18
#define W4 (W/4)            // 56 float4 per row

__device__ float g_pooled[BC * NS];
__device__ unsigned int g_cnt[B];    // monotonic ticket counters (never reset)

__constant__ float c_prior[36] = {
    1.0f,  0.0f,  0.6f,  0.0f, -2.0f, 0.0f,
    0.0f,  1.0f,  0.6f,  0.0f,  0.0f, 0.0f,
    0.1f,  0.1f,  0.5f,  0.0f,  0.0f, 0.0f,
    0.0f,  0.0f,  0.0f,  1.0f,  0.0f, 0.0f,
    0.0f,  0.0f,  0.0f,  0.0f,  1.0f, 0.2f,
    0.0f, -0.6f, -0.6f, -0.6f,  0.6f, 1.0f
};
__constant__ float c_sign[6] = {1.f, -1.f, 1.f, -1.f, 1.f, 1.f};

__device__ __forceinline__ float tanh_f(float x) {
    float y;
    asm("tanh.approx.f32 %0, %1;" : "=f"(y) : "f"(x));
    return y;
}

__device__ __forceinline__ void load_window(
    float4* dst, const float* __restrict__ xc, int win, int sub, int c4)
{
    const int py = win / POOL, px = win - py * POOL;
    const float4* __restrict__ base =
        (const float4*)(xc + (py * 32 + sub) * W + px * 32) + c4;
    #pragma unroll
    for (int r = 0; r < 8; ++r) dst[r] = base[r * W];  // rows sub, sub+4, ...
}

// ---------------------------------------------------------------------------
// r11's proven 70.6us kernel shape + replay-safe ticket barrier (no 2nd launch)
// Block = (batch b, concept d), 256 thr, 3 blocks/SM (regfile-capped).
//  1. stats: stream own 200KB channel (fp32 sum/sumsq)
//  2. windows: gate (tanh) + 32x32 pool, L2 re-read (89MB < 126MB L2),
//     depth-2 window register prefetch
//  3. ticket barrier per batch: monotonic counter, each replay adds exactly C,
//     target = (ticket/C + 1)*C -> deterministic, no reset kernel
//  4. mixing + features + bilinear upsample; staggered blocks overlap these
//     writes with other blocks' phase-1/2 reads (DRAM ~50% busy)
// ---------------------------------------------------------------------------
__global__ __launch_bounds__(256, 3)
void fused_kernel(const float* __restrict__ x,
                  const float* __restrict__ P_delta,
                  float* __restrict__ feat_out,
                  float* __restrict__ out)
{
    extern __shared__ float smem_pad[];            // occupancy control (unused)
    __shared__ float ra[8], rb[8];
    __shared__ float s_sc, s_of;
    __shared__ float xs[CS], sal[CS], tmp[NS];
    __shared__ float Pcol[C], smean[C];
    __shared__ __align__(16) float g[52];
    __shared__ __align__(16) float4 hr4[POOL * W4];

    const int bc = blockIdx.x;
    const int b = bc / C, d = bc - b * C;
    const int tid = threadIdx.x;
    const int warp = tid >> 5, lane = tid & 31;
    const float* __restrict__ xc = x + (size_t)bc * HWSZ;
    if (tid > 100000) smem_pad[0] = 0.f;           // keep pad alive

    // ---- phase 1: stats (49 float4 per thread, batches of 8) ----
    {
        const float4* __restrict__ xin = (const float4*)xc;
        float sum = 0.f, sq = 0.f;
        #pragma unroll
        for (int base = 0; base < 48; base += 8) {
            float4 v[8];
            #pragma unroll
            for (int k = 0; k < 8; ++k) v[k] = xin[(base + k) * 256 + tid];
            #pragma unroll
            for (int k = 0; k < 8; ++k) {
                sum += (v[k].x + v[k].y) + (v[k].z + v[k].w);
                sq  += fmaf(v[k].x, v[k].x, fmaf(v[k].y, v[k].y,
                       fmaf(v[k].z, v[k].z, v[k].w * v[k].w)));
            }
        }
        {
            float4 v = xin[48 * 256 + tid];
            sum += (v.x + v.y) + (v.z + v.w);
            sq  += fmaf(v.x, v.x, fmaf(v.y, v.y, fmaf(v.z, v.z, v.w * v.w)));
        }
        #pragma unroll
        for (int o = 16; o; o >>= 1) {
            sum += __shfl_down_sync(0xffffffffu, sum, o);
            sq  += __shfl_down_sync(0xffffffffu, sq,  o);
        }
        if (lane == 0) { ra[warp] = sum; rb[warp] = sq; }
        __syncthreads();
        if (warp == 0) {
            float s = (lane < 8) ? ra[lane] : 0.f;
            float q = (lane < 8) ? rb[lane] : 0.f;
            #pragma unroll
            for (int o = 4; o; o >>= 1) {
                s += __shfl_down_sync(0xffffffffu, s, o);
                q += __shfl_down_sync(0xffffffffu, q, o);
            }
            if (lane == 0) {
                const float invN = 1.0f / (float)HWSZ;
                float mean = s * invN;
                float var = fmaxf((q - s * s * invN)
                                  * (1.0f / (float)(HWSZ - 1)), 0.f);
                float is = 1.0f / (sqrtf(var) + 1e-5f);
                s_sc = is; s_of = -mean * is;
            }
        }
        __syncthreads();
    }
    const float sc = s_sc, of = s_of;

    // ---- phase 2: windows (8 warps, depth-2 prefetch pipeline) ----
    {
        const int sub = lane >> 3, c4 = lane & 7;
        float4 cur[8], nxt[8];
        load_window(cur, xc, warp, sub, c4);
        for (int win = warp; win < NS; win += 8) {
            if (win + 8 < NS) load_window(nxt, xc, win + 8, sub, c4);
            float acc = 0.f;
            #pragma unroll
            for (int r = 0; r < 8; ++r) {
                acc += tanh_f(fmaf(cur[r].x, sc, of));
                acc += tanh_f(fmaf(cur[r].y, sc, of));
                acc += tanh_f(fmaf(cur[r].z, sc, of));
                acc += tanh_f(fmaf(cur[r].w, sc, of));
            }
            #pragma unroll
            for (int o = 16; o; o >>= 1)
                acc += __shfl_down_sync(0xffffffffu, acc, o);
            if (lane == 0)
                g_pooled[bc * NS + win] = acc * (1.0f / 2048.0f) + 0.5f;
            #pragma unroll
            for (int r = 0; r < 8; ++r) cur[r] = nxt[r];
        }
    }
    __syncthreads();

    // ---- phase 3: ticket barrier (monotonic, replay-safe, no reset) ----
    if (tid == 0) {
        __threadfence();
        unsigned int ticket = atomicAdd(&g_cnt[b], 1u);
        unsigned int target = (ticket / C + 1u) * C;
        while (atomicAdd(&g_cnt[b], 0u) < target) __nanosleep(256);
    }
    __syncthreads();
    __threadfence();

    // ---- phase 4a: mixing ----
    for (int i = tid; i < CS; i += 256) xs[i] = __ldcg(&g_pooled[b * CS + i]);
    if (tid < C) Pcol[tid] = c_prior[tid * 6 + d] + 0.2f * tanhf(P_delta[tid * 6 + d]);
    __syncthreads();

    if (tid < C) {
        float m = 0.f;
        #pragma unroll
        for (int s = 0; s < NS; ++s) m += xs[tid * NS + s];
        smean[tid] = m * (1.0f / (float)NS);
    }
    __syncthreads();

    for (int i = tid; i < CS; i += 256) {
        const int cc = i / NS;
        sal[i] = fmaxf(c_sign[cc] * (xs[i] - smean[cc]), 0.0f);
    }
    __syncthreads();

    if (tid < NS) {
        tmp[tid] = sal[tid]        * Pcol[0] + sal[NS + tid]   * Pcol[1]
                 + sal[2*NS + tid] * Pcol[2] + sal[3*NS + tid] * Pcol[3]
                 + sal[4*NS + tid] * Pcol[4] + sal[5*NS + tid] * Pcol[5];
    }
    __syncthreads();

    if (tid < NS) {
        const int ty = tid / POOL, tx = tid - ty * POOL;
        float acc = 0.f;
        int s = 0;
        #pragma unroll
        for (int sy = 0; sy < POOL; ++sy) {
            const float dy2 = (float)((sy - ty) * (sy - ty));
            #pragma unroll
            for (int sx = 0; sx < POOL; ++sx, ++s) {
                const float dx = (float)(sx - tx);
                acc += __expf(-(dy2 + dx * dx) * 0.78125f) * tmp[s];
            }
        }
        g[tid] = c_sign[d] * fmaxf(acc, 0.0f);
    }
    __syncthreads();

    // ---- phase 4b: features ----
    if (tid < 32) {
        float a  = g[tid];
        bool hi  = (tid + 32) < NS;
        float b2 = hi ? g[tid + 32] : 0.f;
        float s  = a + b2;
        float mx = hi ? fmaxf(a, b2) : a;
        float mn = hi ? fminf(a, b2) : a;
        #pragma unroll
        for (int o = 16; o; o >>= 1) {
            s  += __shfl_down_sync(0xffffffffu, s,  o);
            mx  = fmaxf(mx, __shfl_down_sync(0xffffffffu, mx, o));
            mn  = fminf(mn, __shfl_down_sync(0xffffffffu, mn, o));
        }
        if (tid == 0) {
            feat_out[b * FEAT + d]         = s * (1.0f / (float)NS);
            feat_out[b * FEAT + C + d]     = mx;
            feat_out[b * FEAT + 2 * C + d] = mn;
        }
    }

    // ---- phase 4c: horizontal interpolation table ----
    {
        float* hrows = (float*)hr4;
        for (int i = tid; i < POOL * W; i += 256) {
            const int r = i / W, j = i - r * W;
            const float sx = (j + 0.5f) * (1.0f / 32.0f) - 0.5f;
            const float x0f = floorf(sx);
            const float fx = sx - x0f;
            const int x0 = max(0, min(6, (int)x0f));
            const int x1 = max(0, min(6, (int)x0f + 1));
            const float a = g[r * POOL + x0];
            hrows[r * W + j] = a + fx * (g[r * POOL + x1] - a);
        }
    }
    __syncthreads();

    // ---- phase 4d: vertical pass + streaming stores (448 items / 256 thr) ----
    float4* __restrict__ obase = (float4*)(out + (size_t)bc * HWSZ);
    for (int it = tid; it < 448; it += 256) {
        const int s  = it / W4;          // 0..7 row segment
        const int c4 = it - s * W4;      // 0..55
        const bool edge = (s == 0) | (s == 7);
        const int y0 = (s == 0) ? 0 : (s - 1);
        const int y1 = (s == 7) ? 6 : s;
        const int row0 = (s == 0) ? 0 : (32 * s - 16);
        const int n = edge ? 16 : 32;

        const float4 a  = hr4[y0 * W4 + c4];
        const float4 bb = hr4[y1 * W4 + c4];
        const float dxv = bb.x - a.x, dyv = bb.y - a.y;
        const float dzv = bb.z - a.z, dwv = bb.w - a.w;

        float4* __restrict__ o = obase + row0 * W4 + c4;
        #pragma unroll
        for (int r = 0; r < 32; ++r) {
            if (r < n) {
                const float fy = 0.015625f + (float)r * 0.03125f;
                float4 vv;
                vv.x = fmaf(fy, dxv, a.x);
                vv.y = fmaf(fy, dyv, a.y);
                vv.z = fmaf(fy, dzv, a.z);
                vv.w = fmaf(fy, dwv, a.w);
                __stcs(&o[r * W4], vv);
            }
        }
    }
}

// ---------------------------------------------------------------------------
extern "C" void kernel_launch(void* const* d_in, const int* in_sizes, int n_in,
                              void* d_out, int out_size)
{
    const float* x       = (const float*)d_in[0];   // (128,6,224,224) f32
    const float* P_delta = (const float*)d_in[1];   // (6,6) f32
    float* out = (float*)d_out;                     // [B*18 | B*C*H*W]

    const int PAD = 40 * 1024;    // dynamic smem pad (r11-proven config)
    cudaFuncSetAttribute(fused_kernel,
                         cudaFuncAttributeMaxDynamicSharedMemorySize, PAD);

    fused_kernel<<<BC, 256, PAD>>>(x, P_delta, out, out + (size_t)B * FEAT);
}

// round 15
// speedup vs baseline: 1.0500x; 1.0500x over previous
#include <cuda_runtime.h>
#include <math.h>

#define B 128
#define C 6
#define H 224
#define W 224
#define HWSZ (H*W)          // 50176
#define HW4 (HWSZ/4)        // 12544 float4 per channel
#define POOL 7
#define NS (POOL*POOL)      // 49
#define BC (B*C)            // 768
#define CS (C*NS)           // 294
#define FEAT (3*C)          // 18
#define W4 (W/4)            // 56 float4 per row
#define NT1 512
#define NT2 896

__device__ float g_pooled[BC * NS];

__constant__ float c_prior[36] = {
    1.0f,  0.0f,  0.6f,  0.0f, -2.0f, 0.0f,
    0.0f,  1.0f,  0.6f,  0.0f,  0.0f, 0.0f,
    0.1f,  0.1f,  0.5f,  0.0f,  0.0f, 0.0f,
    0.0f,  0.0f,  0.0f,  1.0f,  0.0f, 0.0f,
    0.0f,  0.0f,  0.0f,  0.0f,  1.0f, 0.2f,
    0.0f, -0.6f, -0.6f, -0.6f,  0.6f, 1.0f
};
__constant__ float c_sign[6] = {1.f, -1.f, 1.f, -1.f, 1.f, 1.f};

__device__ __forceinline__ float tanh_f(float x) {
    float y;
    asm("tanh.approx.f32 %0, %1;" : "=f"(y) : "f"(x));
    return y;
}

// gate + pool one 32x32 window of channel xc (reads hit L2).
__device__ __forceinline__ void do_window(
    const float* __restrict__ xc, float sc, float of,
    int win, int lane, float* __restrict__ out)
{
    const int sub = lane >> 3, c4 = lane & 7;
    const int py = win / POOL, px = win - py * POOL;
    const float4* __restrict__ base =
        (const float4*)(xc + (py * 32 + sub) * W + px * 32) + c4;
    float acc = 0.f;
    #pragma unroll
    for (int r = 0; r < 8; ++r) {               // rows sub, sub+4, ..., sub+28
        float4 u = base[r * W];
        acc += tanh_f(fmaf(u.x, sc, of));
        acc += tanh_f(fmaf(u.y, sc, of));
        acc += tanh_f(fmaf(u.z, sc, of));
        acc += tanh_f(fmaf(u.w, sc, of));
    }
    #pragma unroll
    for (int o = 16; o; o >>= 1) acc += __shfl_down_sync(0xffffffffu, acc, o);
    if (lane == 0) *out = acc * (1.0f / 2048.0f) + 0.5f;
}

// ---------------------------------------------------------------------------
// Kernel 1 (r10-proven, 48us): one block per BATCH, 512 threads.
// Software pipeline per channel stage c:
//   [wins 0-15]  [consume reg-batch A of ch c+1, issue batch B]
//   [wins 16-31] [consume B, block-reduce stats]
//   [wins 32-48] [finalize stats c+1, issue batch A of ch c+2]
// ---------------------------------------------------------------------------
__global__ __launch_bounds__(NT1, 1)
void gate_pool_kernel(const float* __restrict__ x)
{
    __shared__ float ra[16], rb[16];
    __shared__ float s_sc, s_of;

    const int b = blockIdx.x;
    const float* __restrict__ xb = x + (size_t)b * (C * HWSZ);
    const int tid = threadIdx.x;
    const int warp = tid >> 5, lane = tid & 31;
    const bool tl = tid < 256;

    float4 v[12], vt;
    float psum, psq;

    #define LOAD_A(pp) do { \
        _Pragma("unroll") for (int k = 0; k < 12; ++k) v[k] = (pp)[k * NT1 + tid]; \
        if (tl) vt = (pp)[12288 + tid]; } while (0)
    #define LOAD_B(pp) do { \
        _Pragma("unroll") for (int k = 0; k < 12; ++k) v[k] = (pp)[6144 + k * NT1 + tid]; } while (0)
    #define ACC_V() do { \
        _Pragma("unroll") for (int k = 0; k < 12; ++k) { \
            psum += (v[k].x + v[k].y) + (v[k].z + v[k].w); \
            psq  += fmaf(v[k].x, v[k].x, fmaf(v[k].y, v[k].y, \
                    fmaf(v[k].z, v[k].z, v[k].w * v[k].w))); } } while (0)
    #define ACC_T() do { if (tl) { \
            psum += (vt.x + vt.y) + (vt.z + vt.w); \
            psq  += fmaf(vt.x, vt.x, fmaf(vt.y, vt.y, \
                    fmaf(vt.z, vt.z, vt.w * vt.w))); } } while (0)
    #define REDUCE_STATS() do { \
        _Pragma("unroll") for (int o = 16; o; o >>= 1) { \
            psum += __shfl_down_sync(0xffffffffu, psum, o); \
            psq  += __shfl_down_sync(0xffffffffu, psq,  o); } \
        if (lane == 0) { ra[warp] = psum; rb[warp] = psq; } } while (0)
    #define FINAL_STATS() do { \
        if (warp == 0) { \
            float s = (lane < 16) ? ra[lane] : 0.f; \
            float q = (lane < 16) ? rb[lane] : 0.f; \
            _Pragma("unroll") for (int o = 8; o; o >>= 1) { \
                s += __shfl_down_sync(0xffffffffu, s, o); \
                q += __shfl_down_sync(0xffffffffu, q, o); } \
            if (lane == 0) { \
                const float invN = 1.0f / (float)HWSZ; \
                float mean = s * invN; \
                float var = fmaxf((q - s * s * invN) * (1.0f / (float)(HWSZ - 1)), 0.f); \
                float is = 1.0f / (sqrtf(var) + 1e-5f); \
                s_sc = is; s_of = -mean * is; } } } while (0)

    // ---- prologue: channel 0 stats, prefetch A(1) ----
    {
        const float4* p0 = (const float4*)xb;
        LOAD_A(p0);
        psum = 0.f; psq = 0.f;
        ACC_V(); ACC_T();
        LOAD_B(p0);
        ACC_V();
        REDUCE_STATS();
        __syncthreads();
        FINAL_STATS();
        const float4* p1 = (const float4*)(xb + HWSZ);
        LOAD_A(p1);
        __syncthreads();
    }

    // ---- main pipeline ----
    for (int c = 0; c < C; ++c) {
        const float sc = s_sc, of = s_of;
        const float* xc = xb + (size_t)c * HWSZ;
        float* pooled = &g_pooled[(b * C + c) * NS];

        do_window(xc, sc, of, warp, lane, pooled + warp);           // 0..15

        psum = 0.f; psq = 0.f;
        if (c < C - 1) {
            ACC_V(); ACC_T();
            const float4* pn = (const float4*)(xb + (size_t)(c + 1) * HWSZ);
            LOAD_B(pn);
        }

        do_window(xc, sc, of, 16 + warp, lane, pooled + 16 + warp); // 16..31

        if (c < C - 1) {
            ACC_V();
            REDUCE_STATS();
        }

        do_window(xc, sc, of, 32 + warp, lane, pooled + 32 + warp); // 32..47
        if (warp == 0)
            do_window(xc, sc, of, 48, lane, pooled + 48);           // 48

        __syncthreads();
        if (c < C - 1) {
            FINAL_STATS();
            if (c < C - 2) {
                const float4* p2 = (const float4*)(xb + (size_t)(c + 2) * HWSZ);
                LOAD_A(p2);
            }
            __syncthreads();
        }
    }
}

// ---------------------------------------------------------------------------
// Kernel 2: graph mixing + features + structured upsample, 896 threads.
// Thread = (segment s in 0..7, float4-column c4 in 0..55, row-half hh in 0..1)
// -> 16-store chains (was 32), 2 blocks/SM = 1792 store-stream threads.
// ---------------------------------------------------------------------------
__global__ __launch_bounds__(NT2, 2)
void graph_upsample_kernel(const float* __restrict__ P_delta,
                           float* __restrict__ feat_out,
                           float* __restrict__ out)
{
    __shared__ float xs[CS], sal[CS], tmp[NS];
    __shared__ float Pcol[C], smean[C];
    __shared__ __align__(16) float g[52];
    __shared__ __align__(16) float4 hr4[POOL * W4];   // 7 x 56 float4

    const int bc = blockIdx.x;
    const int b = bc / C, d = bc - b * C;
    const int t = threadIdx.x;

    for (int i = t; i < CS; i += NT2) xs[i] = g_pooled[b * CS + i];
    if (t < C) Pcol[t] = c_prior[t * 6 + d] + 0.2f * tanhf(P_delta[t * 6 + d]);
    __syncthreads();

    if (t < C) {
        float m = 0.f;
        #pragma unroll
        for (int s = 0; s < NS; ++s) m += xs[t * NS + s];
        smean[t] = m * (1.0f / (float)NS);
    }
    __syncthreads();

    if (t < CS) {
        const int cc = t / NS;
        sal[t] = fmaxf(c_sign[cc] * (xs[t] - smean[cc]), 0.0f);
    }
    __syncthreads();

    if (t < NS) {
        tmp[t] = sal[t]        * Pcol[0] + sal[NS + t]   * Pcol[1]
               + sal[2*NS + t] * Pcol[2] + sal[3*NS + t] * Pcol[3]
               + sal[4*NS + t] * Pcol[4] + sal[5*NS + t] * Pcol[5];
    }
    __syncthreads();

    if (t < NS) {
        const int ty = t / POOL, tx = t - ty * POOL;
        float acc = 0.f;
        int s = 0;
        #pragma unroll
        for (int sy = 0; sy < POOL; ++sy) {
            const float dy2 = (float)((sy - ty) * (sy - ty));
            #pragma unroll
            for (int sx = 0; sx < POOL; ++sx, ++s) {
                const float dx = (float)(sx - tx);
                acc += __expf(-(dy2 + dx * dx) * 0.78125f) * tmp[s];
            }
        }
        g[t] = c_sign[d] * fmaxf(acc, 0.0f);
    }
    __syncthreads();

    if (t < 32) {
        float a  = g[t];
        bool hi  = (t + 32) < NS;
        float b2 = hi ? g[t + 32] : 0.f;
        float s  = a + b2;
        float mx = hi ? fmaxf(a, b2) : a;
        float mn = hi ? fminf(a, b2) : a;
        #pragma unroll
        for (int o = 16; o; o >>= 1) {
            s  += __shfl_down_sync(0xffffffffu, s,  o);
            mx  = fmaxf(mx, __shfl_down_sync(0xffffffffu, mx, o));
            mn  = fminf(mn, __shfl_down_sync(0xffffffffu, mn, o));
        }
        if (t == 0) {
            feat_out[b * FEAT + d]         = s * (1.0f / (float)NS);
            feat_out[b * FEAT + C + d]     = mx;
            feat_out[b * FEAT + 2 * C + d] = mn;
        }
    }

    {
        float* hrows = (float*)hr4;
        for (int i = t; i < POOL * W; i += NT2) {
            const int r = i / W, j = i - r * W;
            const float sx = (j + 0.5f) * (1.0f / 32.0f) - 0.5f;
            const float x0f = floorf(sx);
            const float fx = sx - x0f;
            const int x0 = max(0, min(6, (int)x0f));
            const int x1 = max(0, min(6, (int)x0f + 1));
            const float a = g[r * POOL + x0];
            hrows[r * W + j] = a + fx * (g[r * POOL + x1] - a);
        }
    }
    __syncthreads();

    // ---- vertical pass: (segment, column, row-half) per thread ----
    // seg 0: rows 0..15 (y0=y1=0), seg 7: rows 208..223 (y0=y1=6),
    // seg s in 1..6: rows 32s-16..32s+15, fy = 1/64 + r/32.
    {
        const int s   = t / 112;            // 0..7
        const int rem = t - s * 112;
        const int c4  = rem >> 1;           // 0..55
        const int hh  = rem & 1;            // row half
        const bool edge = (s == 0) | (s == 7);
        const int y0 = (s == 0) ? 0 : (s - 1);
        const int y1 = (s == 7) ? 6 : s;
        const int segrow0 = (s == 0) ? 0 : (32 * s - 16);
        const int nh = edge ? 8 : 16;       // rows per half
        const int r0 = hh * nh;             // row offset within segment

        const float4 a  = hr4[y0 * W4 + c4];
        const float4 bb = hr4[y1 * W4 + c4];
        const float dxv = bb.x - a.x, dyv = bb.y - a.y;
        const float dzv = bb.z - a.z, dwv = bb.w - a.w;

        float4* __restrict__ o =
            (float4*)(out + (size_t)bc * HWSZ) + (segrow0 + r0) * W4 + c4;
        #pragma unroll
        for (int r = 0; r < 16; ++r) {
            if (r < nh) {
                const float fy = 0.015625f + (float)(r0 + r) * 0.03125f;
                float4 vv;
                vv.x = fmaf(fy, dxv, a.x);
                vv.y = fmaf(fy, dyv, a.y);
                vv.z = fmaf(fy, dzv, a.z);
                vv.w = fmaf(fy, dwv, a.w);
                __stcs(&o[r * W4], vv);
            }
        }
    }
}

// ---------------------------------------------------------------------------
extern "C" void kernel_launch(void* const* d_in, const int* in_sizes, int n_in,
                              void* d_out, int out_size)
{
    const float* x       = (const float*)d_in[0];   // (128,6,224,224) f32
    const float* P_delta = (const float*)d_in[1];   // (6,6) f32
    float* out = (float*)d_out;                     // [B*18 | B*C*H*W]

    gate_pool_kernel<<<B, NT1>>>(x);
    graph_upsample_kernel<<<BC, NT2>>>(P_delta, out, out + (size_t)B * FEAT);
}

// round 16
// speedup vs baseline: 1.0769x; 1.0256x over previous
#include <cuda_runtime.h>
#include <cuda_fp16.h>
#include <math.h>

#define B 128
#define C 6
#define H 224
#define W 224
#define HWSZ (H*W)          // 50176
#define HW4 (HWSZ/4)        // 12544 float4 per channel
#define HW2 (HWSZ/2)        // 25088 half2 per channel
#define POOL 7
#define NS (POOL*POOL)      // 49
#define BC (B*C)            // 768
#define CS (C*NS)           // 294
#define FEAT (3*C)          // 18
#define W4 (W/4)            // 56 float4 per row
#define WH2 (W/2)           // 112 half2 per row
#define NT1 512

__device__ float g_pooled[BC * NS];

__constant__ float c_prior[36] = {
    1.0f,  0.0f,  0.6f,  0.0f, -2.0f, 0.0f,
    0.0f,  1.0f,  0.6f,  0.0f,  0.0f, 0.0f,
    0.1f,  0.1f,  0.5f,  0.0f,  0.0f, 0.0f,
    0.0f,  0.0f,  0.0f,  1.0f,  0.0f, 0.0f,
    0.0f,  0.0f,  0.0f,  0.0f,  1.0f, 0.2f,
    0.0f, -0.6f, -0.6f, -0.6f,  0.6f, 1.0f
};
__constant__ float c_sign[6] = {1.f, -1.f, 1.f, -1.f, 1.f, 1.f};

__device__ __forceinline__ float tanh_f(float x) {
    float y;
    asm("tanh.approx.f32 %0, %1;" : "=f"(y) : "f"(x));
    return y;
}
__device__ __forceinline__ unsigned h2u(__half2 h) { return *(unsigned*)&h; }

// gate + pool one 32x32 window from the fp16 smem shadow.
// lane = (row-parity r2, half2-col c16); 16 row-pair iterations.
__device__ __forceinline__ void window_sm(
    const __half2* __restrict__ buf, float sc, float of,
    int win, int lane, float* __restrict__ out)
{
    const int r2 = lane >> 4, c16 = lane & 15;
    const int py = win / POOL, px = win - py * POOL;
    const __half2* __restrict__ p = buf + (py * 32 + r2) * WH2 + px * 16 + c16;
    float acc = 0.f;
    #pragma unroll
    for (int rp = 0; rp < 16; ++rp) {            // rows r2, r2+2, ..., r2+30
        float2 f = __half22float2(p[rp * 2 * WH2]);
        acc += tanh_f(fmaf(f.x, sc, of)) + tanh_f(fmaf(f.y, sc, of));
    }
    #pragma unroll
    for (int o = 16; o; o >>= 1) acc += __shfl_down_sync(0xffffffffu, acc, o);
    if (lane == 0) *out = acc * (1.0f / 2048.0f) + 0.5f;
}

// ---------------------------------------------------------------------------
// Kernel 1: one block per BATCH (grid 128, 1/SM), 512 thr, 2x100KB fp16
// double-buffered shadow. Pipeline per channel stage c (ch c in buf[c&1]):
//   [wins 0-15 from smem]  [consume+pack reg-batch A of c+1 -> buf^1; LOAD_B]
//   [wins 16-31]           [consume+pack B; block-reduce stats]
//   [wins 32-48]           [finalize stats; LOAD_A of c+2]
// Single DRAM read per channel; window pass reads smem (no L2 re-read).
// sigmoid pooled = 0.5 + mean(tanh((x-m)/std))/2
// ---------------------------------------------------------------------------
__global__ __launch_bounds__(NT1, 1)
void gate_pool_kernel(const float* __restrict__ x)
{
    extern __shared__ __align__(16) __half2 sbuf[];   // 2 * 25088 half2
    __shared__ float ra[16], rb[16];
    __shared__ float s_sc, s_of;

    const int b = blockIdx.x;
    const float* __restrict__ xb = x + (size_t)b * (C * HWSZ);
    const int tid = threadIdx.x;
    const int warp = tid >> 5, lane = tid & 31;
    const bool tl = tid < 256;

    float4 v[12], vt;
    float psum, psq;

    // per channel: A = [0,6144) + tail [12288,12544), B = [6144,12288)
    #define LOAD_A(pp) do { \
        _Pragma("unroll") for (int k = 0; k < 12; ++k) v[k] = (pp)[k * NT1 + tid]; \
        if (tl) vt = (pp)[12288 + tid]; } while (0)
    #define LOAD_B(pp) do { \
        _Pragma("unroll") for (int k = 0; k < 12; ++k) v[k] = (pp)[6144 + k * NT1 + tid]; } while (0)
    #define ACC_PACK_A(b64) do { \
        _Pragma("unroll") for (int k = 0; k < 12; ++k) { \
            psum += (v[k].x + v[k].y) + (v[k].z + v[k].w); \
            psq  += fmaf(v[k].x, v[k].x, fmaf(v[k].y, v[k].y, \
                    fmaf(v[k].z, v[k].z, v[k].w * v[k].w))); \
            uint2 u; \
            u.x = h2u(__floats2half2_rn(v[k].x, v[k].y)); \
            u.y = h2u(__floats2half2_rn(v[k].z, v[k].w)); \
            (b64)[k * NT1 + tid] = u; } \
        if (tl) { \
            psum += (vt.x + vt.y) + (vt.z + vt.w); \
            psq  += fmaf(vt.x, vt.x, fmaf(vt.y, vt.y, \
                    fmaf(vt.z, vt.z, vt.w * vt.w))); \
            uint2 u; \
            u.x = h2u(__floats2half2_rn(vt.x, vt.y)); \
            u.y = h2u(__floats2half2_rn(vt.z, vt.w)); \
            (b64)[12288 + tid] = u; } } while (0)
    #define ACC_PACK_B(b64) do { \
        _Pragma("unroll") for (int k = 0; k < 12; ++k) { \
            psum += (v[k].x + v[k].y) + (v[k].z + v[k].w); \
            psq  += fmaf(v[k].x, v[k].x, fmaf(v[k].y, v[k].y, \
                    fmaf(v[k].z, v[k].z, v[k].w * v[k].w))); \
            uint2 u; \
            u.x = h2u(__floats2half2_rn(v[k].x, v[k].y)); \
            u.y = h2u(__floats2half2_rn(v[k].z, v[k].w)); \
            (b64)[6144 + k * NT1 + tid] = u; } } while (0)
    #define REDUCE_STATS() do { \
        _Pragma("unroll") for (int o = 16; o; o >>= 1) { \
            psum += __shfl_down_sync(0xffffffffu, psum, o); \
            psq  += __shfl_down_sync(0xffffffffu, psq,  o); } \
        if (lane == 0) { ra[warp] = psum; rb[warp] = psq; } } while (0)
    #define FINAL_STATS() do { \
        if (warp == 0) { \
            float s = (lane < 16) ? ra[lane] : 0.f; \
            float q = (lane < 16) ? rb[lane] : 0.f; \
            _Pragma("unroll") for (int o = 8; o; o >>= 1) { \
                s += __shfl_down_sync(0xffffffffu, s, o); \
                q += __shfl_down_sync(0xffffffffu, q, o); } \
            if (lane == 0) { \
                const float invN = 1.0f / (float)HWSZ; \
                float mean = s * invN; \
                float var = fmaxf((q - s * s * invN) * (1.0f / (float)(HWSZ - 1)), 0.f); \
                float is = 1.0f / (sqrtf(var) + 1e-5f); \
                s_sc = is; s_of = -mean * is; } } } while (0)

    // ---- prologue: channel 0 -> stats + shadow buf0; prefetch A(1) ----
    {
        uint2* b64 = (uint2*)sbuf;
        const float4* p0 = (const float4*)xb;
        LOAD_A(p0);
        psum = 0.f; psq = 0.f;
        ACC_PACK_A(b64);
        LOAD_B(p0);
        ACC_PACK_B(b64);
        REDUCE_STATS();
        __syncthreads();
        FINAL_STATS();
        const float4* p1 = (const float4*)(xb + HWSZ);
        LOAD_A(p1);      // A(1) in flight across stage 0
        __syncthreads();
    }

    // ---- main pipeline ----
    for (int c = 0; c < C; ++c) {
        const float sc = s_sc, of = s_of;
        const __half2* __restrict__ buf = sbuf + (c & 1) * HW2;
        uint2* b64n = (uint2*)(sbuf + ((c + 1) & 1) * HW2);
        float* pooled = &g_pooled[(b * C + c) * NS];

        window_sm(buf, sc, of, warp, lane, pooled + warp);           // 0..15

        psum = 0.f; psq = 0.f;
        if (c < C - 1) {
            ACC_PACK_A(b64n);                     // consume+pack A(c+1)
            const float4* pn = (const float4*)(xb + (size_t)(c + 1) * HWSZ);
            LOAD_B(pn);                           // B(c+1) in flight
        }

        window_sm(buf, sc, of, 16 + warp, lane, pooled + 16 + warp); // 16..31

        if (c < C - 1) {
            ACC_PACK_B(b64n);                     // consume+pack B(c+1)
            REDUCE_STATS();
        }

        window_sm(buf, sc, of, 32 + warp, lane, pooled + 32 + warp); // 32..47
        if (warp == 0)
            window_sm(buf, sc, of, 48, lane, pooled + 48);           // 48

        __syncthreads();
        if (c < C - 1) {
            FINAL_STATS();
            if (c < C - 2) {
                const float4* p2 = (const float4*)(xb + (size_t)(c + 2) * HWSZ);
                LOAD_A(p2);                       // A(c+2) in flight
            }
            __syncthreads();
        }
    }
}

// ---------------------------------------------------------------------------
// Kernel 2 (r6-proven, 27.8us): graph mixing + features + structured upsample.
// 448 threads: thread = (segment s in 0..7, float4-column c4 in 0..55).
// ---------------------------------------------------------------------------
__global__ __launch_bounds__(448)
void graph_upsample_kernel(const float* __restrict__ P_delta,
                           float* __restrict__ feat_out,
                           float* __restrict__ out)
{
    __shared__ float xs[CS], sal[CS], tmp[NS];
    __shared__ float Pcol[C], smean[C];
    __shared__ __align__(16) float g[52];
    __shared__ __align__(16) float4 hr4[POOL * W4];   // 7 x 56 float4

    const int bc = blockIdx.x;
    const int b = bc / C, d = bc - b * C;
    const int t = threadIdx.x;

    for (int i = t; i < CS; i += 448) xs[i] = g_pooled[b * CS + i];
    if (t < C) Pcol[t] = c_prior[t * 6 + d] + 0.2f * tanhf(P_delta[t * 6 + d]);
    __syncthreads();

    if (t < C) {
        float m = 0.f;
        #pragma unroll
        for (int s = 0; s < NS; ++s) m += xs[t * NS + s];
        smean[t] = m * (1.0f / (float)NS);
    }
    __syncthreads();

    if (t < CS) {
        const int cc = t / NS;
        sal[t] = fmaxf(c_sign[cc] * (xs[t] - smean[cc]), 0.0f);
    }
    __syncthreads();

    if (t < NS) {
        tmp[t] = sal[t]        * Pcol[0] + sal[NS + t]   * Pcol[1]
               + sal[2*NS + t] * Pcol[2] + sal[3*NS + t] * Pcol[3]
               + sal[4*NS + t] * Pcol[4] + sal[5*NS + t] * Pcol[5];
    }
    __syncthreads();

    if (t < NS) {
        const int ty = t / POOL, tx = t - ty * POOL;
        float acc = 0.f;
        int s = 0;
        #pragma unroll
        for (int sy = 0; sy < POOL; ++sy) {
            const float dy2 = (float)((sy - ty) * (sy - ty));
            #pragma unroll
            for (int sx = 0; sx < POOL; ++sx, ++s) {
                const float dx = (float)(sx - tx);
                acc += __expf(-(dy2 + dx * dx) * 0.78125f) * tmp[s];
            }
        }
        g[t] = c_sign[d] * fmaxf(acc, 0.0f);
    }
    __syncthreads();

    if (t < 32) {
        float a  = g[t];
        bool hi  = (t + 32) < NS;
        float b2 = hi ? g[t + 32] : 0.f;
        float s  = a + b2;
        float mx = hi ? fmaxf(a, b2) : a;
        float mn = hi ? fminf(a, b2) : a;
        #pragma unroll
        for (int o = 16; o; o >>= 1) {
            s  += __shfl_down_sync(0xffffffffu, s,  o);
            mx  = fmaxf(mx, __shfl_down_sync(0xffffffffu, mx, o));
            mn  = fminf(mn, __shfl_down_sync(0xffffffffu, mn, o));
        }
        if (t == 0) {
            feat_out[b * FEAT + d]         = s * (1.0f / (float)NS);
            feat_out[b * FEAT + C + d]     = mx;
            feat_out[b * FEAT + 2 * C + d] = mn;
        }
    }

    {
        float* hrows = (float*)hr4;
        for (int i = t; i < POOL * W; i += 448) {
            const int r = i / W, j = i - r * W;
            const float sx = (j + 0.5f) * (1.0f / 32.0f) - 0.5f;
            const float x0f = floorf(sx);
            const float fx = sx - x0f;
            const int x0 = max(0, min(6, (int)x0f));
            const int x1 = max(0, min(6, (int)x0f + 1));
            const float a = g[r * POOL + x0];
            hrows[r * W + j] = a + fx * (g[r * POOL + x1] - a);
        }
    }
    __syncthreads();

    {
        const int s  = t / W4;           // 0..7
        const int c4 = t - s * W4;       // 0..55
        const bool edge = (s == 0) | (s == 7);
        const int y0 = (s == 0) ? 0 : (s - 1);
        const int y1 = (s == 7) ? 6 : s;
        const int row0 = (s == 0) ? 0 : (32 * s - 16);
        const int n = edge ? 16 : 32;

        const float4 a = hr4[y0 * W4 + c4];
        const float4 bb = hr4[y1 * W4 + c4];
        const float dxv = bb.x - a.x, dyv = bb.y - a.y;
        const float dzv = bb.z - a.z, dwv = bb.w - a.w;

        float4* __restrict__ o = (float4*)(out + (size_t)bc * HWSZ) + row0 * W4 + c4;
        #pragma unroll
        for (int r = 0; r < 32; ++r) {
            if (r < n) {
                const float fy = 0.015625f + (float)r * 0.03125f;
                float4 vv;
                vv.x = fmaf(fy, dxv, a.x);
                vv.y = fmaf(fy, dyv, a.y);
                vv.z = fmaf(fy, dzv, a.z);
                vv.w = fmaf(fy, dwv, a.w);
                __stcs(&o[r * W4], vv);
            }
        }
    }
}

// ---------------------------------------------------------------------------
extern "C" void kernel_launch(void* const* d_in, const int* in_sizes, int n_in,
                              void* d_out, int out_size)
{
    const float* x       = (const float*)d_in[0];   // (128,6,224,224) f32
    const float* P_delta = (const float*)d_in[1];   // (6,6) f32
    float* out = (float*)d_out;                     // [B*18 | B*C*H*W]

    const int SMEM1 = 2 * HW2 * 4;   // 200704 B double fp16 shadow
    cudaFuncSetAttribute(gate_pool_kernel,
                         cudaFuncAttributeMaxDynamicSharedMemorySize, SMEM1);

    gate_pool_kernel<<<B, NT1, SMEM1>>>(x);
    graph_upsample_kernel<<<BC, 448>>>(P_delta, out, out + (size_t)B * FEAT);
}